// round 16
// baseline (speedup 1.0000x reference)
#include <cuda_runtime.h>
#include <cuda_fp16.h>
#include <cstdint>

// Problem:
//   z:        [32, 512, 32, 32] f32  (B, C, H, W)
//   codebook: [1024, 512] f32        (K, D)
// Outputs (concatenated f32): quantized [16,777,216], then indices [32,768] as float.

#define N_ROWS   32768
#define K_CODES  1024
#define DIM      512
#define HW       1024
#define QUANT_ELEMS 16777216

// pass-1 GEMM config: pure fp16 single-term approximation, K' = 512
#define KTOT 512
#define KC   64            // fp16 per K tile
#define NKT  (KTOT / KC)   // 8
#define PM   128
#define PN   128
#define MARGIN 2.6e-3f     // >= 2x worst-case |d_approx - d_exact| bound (~1.1e-3)

// smem layout (bytes): A0 @0 (18432) | B0 @18432 | A1 @36864 | B1 @55296
#define ROWB   144          // 72 fp16 per row (64 + 8 pad) = 144 B
#define ABYTES 18432        // 128 * 144
#define BUFOFF 36864
#define P1_SMEM 73728

// 16B-aligned global bases for cp.async / float4 paths.
__device__ __align__(256) float  g_codenorm[K_CODES];
__device__ __align__(256) float  g_rownorm[N_ROWS];
__device__ __align__(256) int    g_index[N_ROWS];
__device__ __align__(256) __half g_zbuf[(size_t)N_ROWS * KTOT];   // [row][c] fp16
__device__ __align__(256) __half g_wbuf[(size_t)K_CODES * KTOT];  // [code][c] fp16
__device__ __align__(256) float  g_dist[(size_t)N_ROWS * K_CODES];

// ---------------------------------------------------------------------------
__device__ __forceinline__ void cp_async16(uint32_t saddr, const void* g) {
    asm volatile("cp.async.ca.shared.global [%0], [%1], 16;\n" :: "r"(saddr), "l"(g));
}
#define CP_COMMIT()   asm volatile("cp.async.commit_group;\n" ::: "memory")
#define CP_WAIT(n)    asm volatile("cp.async.wait_group %0;\n" :: "n"(n) : "memory")

__device__ __forceinline__ void ldsm_x4(uint32_t& r0, uint32_t& r1, uint32_t& r2,
                                        uint32_t& r3, uint32_t addr) {
    asm volatile("ldmatrix.sync.aligned.m8n8.x4.shared.b16 {%0,%1,%2,%3}, [%4];"
                 : "=r"(r0), "=r"(r1), "=r"(r2), "=r"(r3) : "r"(addr));
}
__device__ __forceinline__ void mma16816(float* d, const uint32_t* a, const uint32_t* b) {
    asm volatile("mma.sync.aligned.m16n8k16.row.col.f32.f16.f16.f32 "
                 "{%0,%1,%2,%3}, {%4,%5,%6,%7}, {%8,%9}, {%0,%1,%2,%3};"
                 : "+f"(d[0]), "+f"(d[1]), "+f"(d[2]), "+f"(d[3])
                 : "r"(a[0]), "r"(a[1]), "r"(a[2]), "r"(a[3]), "r"(b[0]), "r"(b[1]));
}

// ---------------------------------------------------------------------------
// Preamble: row norms (XLA NEON-4 order) + code norms (same order).
// ---------------------------------------------------------------------------
__global__ void prep_kernel(const float* __restrict__ z, const float* __restrict__ cb) {
    const int blk = blockIdx.x, t = threadIdx.x;
    if (blk < 1024) {
        __shared__ float part[4][32];
        const int j = t >> 5, r = t & 31;
        const int row = blk * 32 + r;
        const int b = row >> 10, hw = row & 1023;
        const float* base = z + (size_t)b * DIM * HW + hw;
        float acc = 0.f;
#pragma unroll 8
        for (int i = 0; i < DIM / 4; ++i) {
            float v = __ldg(base + (size_t)(4 * i + j) * HW);
            acc = __fadd_rn(acc, __fmul_rn(v, v));
        }
        part[j][r] = acc;
        __syncthreads();
        if (t < 32) {
            float u0 = __fadd_rn(part[0][t], part[2][t]);
            float u1 = __fadd_rn(part[1][t], part[3][t]);
            g_rownorm[blk * 32 + t] = __fadd_rn(u0, u1);
        }
    } else {
        const int j = t & 3;
        const int code = (blk - 1024) * 32 + (t >> 2);
        const float* row = cb + (size_t)code * DIM;
        float acc = 0.f;
#pragma unroll 8
        for (int i = 0; i < DIM / 4; ++i) {
            float v = __ldg(row + 4 * i + j);
            acc = __fadd_rn(acc, __fmul_rn(v, v));
        }
        float u = __fadd_rn(acc, __shfl_down_sync(0xffffffffu, acc, 2));
        float c = __fadd_rn(u,   __shfl_down_sync(0xffffffffu, u, 1));
        if (j == 0) g_codenorm[code] = c;
    }
}

// ---------------------------------------------------------------------------
// Convert z -> fp16, transposed to row-major [row][c].
// Scalar smem stores (65-float stride is not 16B-periodic; see R13 fault).
// ---------------------------------------------------------------------------
__global__ void convert_z_kernel(const float* __restrict__ z) {
    __shared__ float s[64][65];
    const int t = threadIdx.x;
    const int row0 = (blockIdx.x >> 3) * 64;
    const int c0   = (blockIdx.x & 7) * 64;
    const int b = row0 >> 10, hw0 = row0 & 1023;
    const float* zb = z + (size_t)b * DIM * HW + hw0;
#pragma unroll
    for (int q = 0; q < 4; ++q) {
        int id = q * 256 + t;
        int cc = id >> 4, f4 = id & 15;
        float4 v = __ldg((const float4*)(zb + (size_t)(c0 + cc) * HW) + f4);
        s[cc][f4 * 4 + 0] = v.x;
        s[cc][f4 * 4 + 1] = v.y;
        s[cc][f4 * 4 + 2] = v.z;
        s[cc][f4 * 4 + 3] = v.w;
    }
    __syncthreads();
#pragma unroll
    for (int q = 0; q < 16; ++q) {
        int id = q * 256 + t;
        int r = id >> 6, cc = id & 63;
        g_zbuf[(size_t)(row0 + r) * KTOT + c0 + cc] = __float2half_rn(s[cc][r]);
    }
}

__global__ void convert_w_kernel(const float* __restrict__ cb) {
    const int code = blockIdx.x;
    const int t = threadIdx.x;
    const float* row = cb + (size_t)code * DIM;
    size_t base = (size_t)code * KTOT;
    for (int c = t; c < DIM; c += 128)
        g_wbuf[base + c] = __float2half_rn(__ldg(row + c));
}

// ---------------------------------------------------------------------------
// Pass 1: approx distance GEMM on mma.sync (fp16 x fp16 -> f32).
// Block 128x128, 256 threads = 8 warps (2 row-groups x 4 col-groups),
// warp tile 64x32 (4 mi x 4 ni m16n8k16 frags), kc=64 double-buffered cp.async.
// ---------------------------------------------------------------------------
__device__ __forceinline__ void load_tile(uint32_t smbase, int rows0, int n0,
                                          int kt, int t, int buf) {
    const int kc0 = kt * KC;
    const uint32_t sa = smbase + buf * BUFOFF;
    const uint32_t sb = sa + ABYTES;
#pragma unroll
    for (int q = 0; q < 4; ++q) {
        int id = q * 256 + t;
        int row = id >> 3, ch = id & 7;
        cp_async16(sa + row * ROWB + ch * 16,
                   g_zbuf + (size_t)(rows0 + row) * KTOT + kc0 + ch * 8);
        cp_async16(sb + row * ROWB + ch * 16,
                   g_wbuf + (size_t)(n0 + row) * KTOT + kc0 + ch * 8);
    }
}

__global__ void __launch_bounds__(256, 2)
pass1_kernel()
{
    extern __shared__ char smraw[];
    const uint32_t smbase = (uint32_t)__cvta_generic_to_shared(smraw);
    const int t = threadIdx.x;
    const int wid = t >> 5, lane = t & 31;
    const int wr = wid & 1, wc = wid >> 1;
    const int rows0 = (blockIdx.x >> 3) * PM;
    const int n0    = (blockIdx.x & 7) * PN;

    // ldmatrix per-lane address components
    const int lr = lane & 7, q = lane >> 3;
    const int a_row = wr * 64 + lr + (q & 1) * 8;
    const int a_koff = (q >> 1) * 8;
    const int b_row = wc * 32 + lr + (q >> 1) * 8;
    const int b_koff = (q & 1) * 8;

    float acc[4][4][4];
#pragma unroll
    for (int mi = 0; mi < 4; ++mi)
#pragma unroll
        for (int ni = 0; ni < 4; ++ni)
#pragma unroll
            for (int e = 0; e < 4; ++e) acc[mi][ni][e] = 0.f;

    load_tile(smbase, rows0, n0, 0, t, 0);
    CP_COMMIT();

    for (int kt = 0; kt < NKT; ++kt) {
        const int p = kt & 1;
        if (kt + 1 < NKT) {
            load_tile(smbase, rows0, n0, kt + 1, t, p ^ 1);
            CP_COMMIT();
            CP_WAIT(1);
        } else {
            CP_WAIT(0);
        }
        __syncthreads();

        const uint32_t sa = smbase + p * BUFOFF;
        const uint32_t sb = sa + ABYTES;
#pragma unroll
        for (int ks = 0; ks < 4; ++ks) {
            const int k0 = ks * 16;
            uint32_t af[4][4], bf[4][2];
#pragma unroll
            for (int mi = 0; mi < 4; ++mi)
                ldsm_x4(af[mi][0], af[mi][1], af[mi][2], af[mi][3],
                        sa + (a_row + mi * 16) * ROWB + (k0 + a_koff) * 2);
#pragma unroll
            for (int np = 0; np < 2; ++np)
                ldsm_x4(bf[2 * np][0], bf[2 * np][1], bf[2 * np + 1][0], bf[2 * np + 1][1],
                        sb + (b_row + np * 16) * ROWB + (k0 + b_koff) * 2);
#pragma unroll
            for (int mi = 0; mi < 4; ++mi)
#pragma unroll
                for (int ni = 0; ni < 4; ++ni)
                    mma16816(acc[mi][ni], af[mi], bf[ni]);
        }
        __syncthreads();
    }

    // epilogue: d = A - 2M + C (approx), stage in smem, coalesced write
    float* ds = reinterpret_cast<float*>(smraw);    // [128][132]
    const int g = lane >> 2, c = (lane & 3) * 2;
#pragma unroll
    for (int mi = 0; mi < 4; ++mi) {
        const int r0 = wr * 64 + mi * 16 + g;
        const float Ar0 = g_rownorm[rows0 + r0];
        const float Ar1 = g_rownorm[rows0 + r0 + 8];
#pragma unroll
        for (int ni = 0; ni < 4; ++ni) {
            const int col = wc * 32 + ni * 8 + c;
            const float cn0 = g_codenorm[n0 + col];
            const float cn1 = g_codenorm[n0 + col + 1];
            ds[r0 * 132 + col]           = fmaf(-2.f, acc[mi][ni][0], Ar0) + cn0;
            ds[r0 * 132 + col + 1]       = fmaf(-2.f, acc[mi][ni][1], Ar0) + cn1;
            ds[(r0 + 8) * 132 + col]     = fmaf(-2.f, acc[mi][ni][2], Ar1) + cn0;
            ds[(r0 + 8) * 132 + col + 1] = fmaf(-2.f, acc[mi][ni][3], Ar1) + cn1;
        }
    }
    __syncthreads();
#pragma unroll
    for (int rr = 0; rr < 16; ++rr) {
        const int row = wid * 16 + rr;
        float4 v = *reinterpret_cast<const float4*>(ds + row * 132 + lane * 4);
        *reinterpret_cast<float4*>(g_dist + (size_t)(rows0 + row) * 1024 + n0 + lane * 4) = v;
    }
}

// ---------------------------------------------------------------------------
// Select + exact rescore. One warp per row.
// Unique candidate within margin => provably the exact argmin.
// Ambiguous => rescore candidates with the reference-exact chain.
// ---------------------------------------------------------------------------
__global__ void __launch_bounds__(256) select_kernel(const float* __restrict__ z,
                                                     const float* __restrict__ cb)
{
    __shared__ int s_list[8][64];
    __shared__ int s_cnt[8];
    const int warp = threadIdx.x >> 5, lane = threadIdx.x & 31;
    const int row = blockIdx.x * 8 + warp;
    const float* dr = g_dist + (size_t)row * 1024;
    if (lane == 0) s_cnt[warp] = 0;
    __syncwarp();

    float dv[32];
    unsigned long long key = ~0ull;
#pragma unroll
    for (int it = 0; it < 8; ++it) {
        float4 v = __ldg((const float4*)dr + it * 32 + lane);
        int i0 = it * 128 + lane * 4;
        dv[it * 4 + 0] = v.x; dv[it * 4 + 1] = v.y;
        dv[it * 4 + 2] = v.z; dv[it * 4 + 3] = v.w;
        unsigned long long k;
        k = ((unsigned long long)__float_as_uint(v.x) << 32) | (unsigned)(i0 + 0); if (k < key) key = k;
        k = ((unsigned long long)__float_as_uint(v.y) << 32) | (unsigned)(i0 + 1); if (k < key) key = k;
        k = ((unsigned long long)__float_as_uint(v.z) << 32) | (unsigned)(i0 + 2); if (k < key) key = k;
        k = ((unsigned long long)__float_as_uint(v.w) << 32) | (unsigned)(i0 + 3); if (k < key) key = k;
    }
#pragma unroll
    for (int o = 16; o > 0; o >>= 1) {
        unsigned long long other = __shfl_xor_sync(0xffffffffu, key, o);
        if (other < key) key = other;
    }
    const float thr = __uint_as_float((uint32_t)(key >> 32)) + MARGIN;
#pragma unroll
    for (int it = 0; it < 8; ++it)
#pragma unroll
        for (int e = 0; e < 4; ++e)
            if (dv[it * 4 + e] <= thr) {
                int pos = atomicAdd(&s_cnt[warp], 1);
                if (pos < 64) s_list[warp][pos] = it * 128 + lane * 4 + e;
            }
    __syncwarp();
    const int cnt = s_cnt[warp];

    int winner;
    if (cnt <= 1) {
        winner = (int)(key & 0xFFFFFFFFull);    // unique candidate == exact argmin
    } else {
        const int b = row >> 10, hw = row & 1023;
        const float* zr = z + (size_t)b * DIM * HW + hw;
        const float Ar = g_rownorm[row];
        const bool full = (cnt > 64);           // safety fallback
        const int total = full ? 1024 : cnt;
        unsigned long long bk = ~0ull;
        for (int base = 0; base < total; base += 32) {
            const int ci = base + lane;
            unsigned long long k2 = ~0ull;
            if (ci < total) {
                const int cand = full ? ci : s_list[warp][ci];
                const float* wr = cb + (size_t)cand * DIM;
                float acc = 0.f;                 // reference-exact chain
#pragma unroll 8
                for (int c = 0; c < DIM; ++c)
                    acc = __fmaf_rn(zr[(size_t)c * HW], wr[c], acc);
                float d = __fadd_rn(__fadd_rn(Ar, __fmul_rn(-2.f, acc)),
                                    g_codenorm[cand]);
                k2 = ((unsigned long long)__float_as_uint(d) << 32) | (unsigned)cand;
            }
            if (k2 < bk) bk = k2;
        }
#pragma unroll
        for (int o = 16; o > 0; o >>= 1) {
            unsigned long long other = __shfl_xor_sync(0xffffffffu, bk, o);
            if (other < bk) bk = other;
        }
        winner = (int)(bk & 0xFFFFFFFFull);
    }
    if (lane == 0) g_index[row] = winner;
}

// ---------------------------------------------------------------------------
// Gather: quantized = codebook[idx]; also writes indices output.
// ---------------------------------------------------------------------------
__global__ void gather_kernel(const float* __restrict__ cb, float* __restrict__ out) {
    int i  = blockIdx.x * blockDim.x + threadIdx.x;
    int n  = i >> 7;
    int dd = i & 127;
    int idx = g_index[n];
    float4 v = __ldg(reinterpret_cast<const float4*>(cb) + (size_t)idx * 128 + dd);
    reinterpret_cast<float4*>(out)[i] = v;
    if (dd == 0) out[QUANT_ELEMS + n] = (float)idx;
}

// ---------------------------------------------------------------------------
extern "C" void kernel_launch(void* const* d_in, const int* in_sizes, int n_in,
                              void* d_out, int out_size) {
    const float* z  = (const float*)d_in[0];
    const float* cb = (const float*)d_in[1];
    float* out = (float*)d_out;

    cudaFuncSetAttribute(pass1_kernel,
                         cudaFuncAttributeMaxDynamicSharedMemorySize, P1_SMEM);

    prep_kernel<<<1024 + K_CODES / 32, 128>>>(z, cb);
    convert_z_kernel<<<(N_ROWS / 64) * 8, 256>>>(z);
    convert_w_kernel<<<K_CODES, 128>>>(cb);
    pass1_kernel<<<(N_ROWS / PM) * (K_CODES / PN), 256, P1_SMEM>>>();
    select_kernel<<<N_ROWS / 8, 256>>>(z, cb);
    gather_kernel<<<QUANT_ELEMS / 4 / 256, 256>>>(cb, out);
}

// round 17
// speedup vs baseline: 1.0431x; 1.0431x over previous
#include <cuda_runtime.h>
#include <cuda_fp16.h>
#include <cstdint>

// Problem:
//   z:        [32, 512, 32, 32] f32  (B, C, H, W)
//   codebook: [1024, 512] f32        (K, D)
// Outputs (concatenated f32): quantized [16,777,216], then indices [32,768] as float.

#define N_ROWS   32768
#define K_CODES  1024
#define DIM      512
#define HW       1024
#define QUANT_ELEMS 16777216

// pass-1 GEMM config: pure fp16 single-term approximation, K' = 512
#define KTOT 512
#define KC   64            // fp16 per K tile
#define NKT  (KTOT / KC)   // 8
#define PM   128
#define PN   128
// bound: fp16-gemm ~1.0e-3 + reference fl() reorder 2.6e-4 + f16 score storage 1.3e-4
#define MARGIN 2.8e-3f

// smem layout (bytes): A0 @0 (18432) | B0 @18432 | A1 @36864 | B1 @55296
#define ROWB   144          // 72 fp16 per row (64 + 8 pad) = 144 B
#define ABYTES 18432        // 128 * 144
#define BUFOFF 36864
#define P1_SMEM 73728

// 16B-aligned global bases for cp.async / float4 paths.
__device__ __align__(256) float  g_codenorm[K_CODES];
__device__ __align__(256) float  g_rownorm[N_ROWS];
__device__ __align__(256) int    g_index[N_ROWS];
__device__ __align__(256) __half g_zbuf[(size_t)N_ROWS * KTOT];   // [row][c] fp16
__device__ __align__(256) __half g_wbuf[(size_t)K_CODES * KTOT];  // [code][c] fp16
__device__ __align__(256) __half g_score[(size_t)N_ROWS * K_CODES]; // s = C - 2M (fp16)

// ---------------------------------------------------------------------------
__device__ __forceinline__ void cp_async16(uint32_t saddr, const void* g) {
    asm volatile("cp.async.ca.shared.global [%0], [%1], 16;\n" :: "r"(saddr), "l"(g));
}
#define CP_COMMIT()   asm volatile("cp.async.commit_group;\n" ::: "memory")
#define CP_WAIT(n)    asm volatile("cp.async.wait_group %0;\n" :: "n"(n) : "memory")

__device__ __forceinline__ void ldsm_x4(uint32_t& r0, uint32_t& r1, uint32_t& r2,
                                        uint32_t& r3, uint32_t addr) {
    asm volatile("ldmatrix.sync.aligned.m8n8.x4.shared.b16 {%0,%1,%2,%3}, [%4];"
                 : "=r"(r0), "=r"(r1), "=r"(r2), "=r"(r3) : "r"(addr));
}
__device__ __forceinline__ void mma16816(float* d, const uint32_t* a, const uint32_t* b) {
    asm volatile("mma.sync.aligned.m16n8k16.row.col.f32.f16.f16.f32 "
                 "{%0,%1,%2,%3}, {%4,%5,%6,%7}, {%8,%9}, {%0,%1,%2,%3};"
                 : "+f"(d[0]), "+f"(d[1]), "+f"(d[2]), "+f"(d[3])
                 : "r"(a[0]), "r"(a[1]), "r"(a[2]), "r"(a[3]), "r"(b[0]), "r"(b[1]));
}

// ---------------------------------------------------------------------------
// Preamble: row norms (XLA NEON-4 order) + code norms (same order).
// ---------------------------------------------------------------------------
__global__ void prep_kernel(const float* __restrict__ z, const float* __restrict__ cb) {
    const int blk = blockIdx.x, t = threadIdx.x;
    if (blk < 1024) {
        __shared__ float part[4][32];
        const int j = t >> 5, r = t & 31;
        const int row = blk * 32 + r;
        const int b = row >> 10, hw = row & 1023;
        const float* base = z + (size_t)b * DIM * HW + hw;
        float acc = 0.f;
#pragma unroll 8
        for (int i = 0; i < DIM / 4; ++i) {
            float v = __ldg(base + (size_t)(4 * i + j) * HW);
            acc = __fadd_rn(acc, __fmul_rn(v, v));
        }
        part[j][r] = acc;
        __syncthreads();
        if (t < 32) {
            float u0 = __fadd_rn(part[0][t], part[2][t]);
            float u1 = __fadd_rn(part[1][t], part[3][t]);
            g_rownorm[blk * 32 + t] = __fadd_rn(u0, u1);
        }
    } else {
        const int j = t & 3;
        const int code = (blk - 1024) * 32 + (t >> 2);
        const float* row = cb + (size_t)code * DIM;
        float acc = 0.f;
#pragma unroll 8
        for (int i = 0; i < DIM / 4; ++i) {
            float v = __ldg(row + 4 * i + j);
            acc = __fadd_rn(acc, __fmul_rn(v, v));
        }
        float u = __fadd_rn(acc, __shfl_down_sync(0xffffffffu, acc, 2));
        float c = __fadd_rn(u,   __shfl_down_sync(0xffffffffu, u, 1));
        if (j == 0) g_codenorm[code] = c;
    }
}

// ---------------------------------------------------------------------------
// Convert z -> fp16, transposed to row-major [row][c].
// Scalar smem stores (65-float stride is not 16B-periodic; see R13 fault).
// ---------------------------------------------------------------------------
__global__ void convert_z_kernel(const float* __restrict__ z) {
    __shared__ float s[64][65];
    const int t = threadIdx.x;
    const int row0 = (blockIdx.x >> 3) * 64;
    const int c0   = (blockIdx.x & 7) * 64;
    const int b = row0 >> 10, hw0 = row0 & 1023;
    const float* zb = z + (size_t)b * DIM * HW + hw0;
#pragma unroll
    for (int q = 0; q < 4; ++q) {
        int id = q * 256 + t;
        int cc = id >> 4, f4 = id & 15;
        float4 v = __ldg((const float4*)(zb + (size_t)(c0 + cc) * HW) + f4);
        s[cc][f4 * 4 + 0] = v.x;
        s[cc][f4 * 4 + 1] = v.y;
        s[cc][f4 * 4 + 2] = v.z;
        s[cc][f4 * 4 + 3] = v.w;
    }
    __syncthreads();
#pragma unroll
    for (int q = 0; q < 16; ++q) {
        int id = q * 256 + t;
        int r = id >> 6, cc = id & 63;
        g_zbuf[(size_t)(row0 + r) * KTOT + c0 + cc] = __float2half_rn(s[cc][r]);
    }
}

__global__ void convert_w_kernel(const float* __restrict__ cb) {
    const int code = blockIdx.x;
    const int t = threadIdx.x;
    const float* row = cb + (size_t)code * DIM;
    size_t base = (size_t)code * KTOT;
    for (int c = t; c < DIM; c += 128)
        g_wbuf[base + c] = __float2half_rn(__ldg(row + c));
}

// ---------------------------------------------------------------------------
// Pass 1: approx score GEMM on mma.sync (fp16 x fp16 -> f32).
// Block 128x128, 128 threads = 4 warps (2 row x 2 col groups),
// warp tile 64x64 (4 mi x 8 ni m16n8k16 frags) -> 8 ldsm per 32 MMA.
// Writes s = C - 2M as fp16 (A is per-row constant; argmin preserved).
// ---------------------------------------------------------------------------
__device__ __forceinline__ void load_tile(uint32_t smbase, int rows0, int n0,
                                          int kt, int t, int buf) {
    const int kc0 = kt * KC;
    const uint32_t sa = smbase + buf * BUFOFF;
    const uint32_t sb = sa + ABYTES;
#pragma unroll
    for (int q = 0; q < 8; ++q) {
        int id = q * 128 + t;
        int row = id >> 3, ch = id & 7;
        cp_async16(sa + row * ROWB + ch * 16,
                   g_zbuf + (size_t)(rows0 + row) * KTOT + kc0 + ch * 8);
        cp_async16(sb + row * ROWB + ch * 16,
                   g_wbuf + (size_t)(n0 + row) * KTOT + kc0 + ch * 8);
    }
}

__global__ void __launch_bounds__(128, 2)
pass1_kernel()
{
    extern __shared__ char smraw[];
    const uint32_t smbase = (uint32_t)__cvta_generic_to_shared(smraw);
    const int t = threadIdx.x;
    const int wid = t >> 5, lane = t & 31;
    const int wr = wid >> 1, wc = wid & 1;      // 2x2 warp grid, 64x64 tiles
    const int rows0 = (blockIdx.x >> 3) * PM;
    const int n0    = (blockIdx.x & 7) * PN;

    // ldmatrix per-lane address components (mapping validated in R14/R16)
    const int lr = lane & 7, q = lane >> 3;
    const int a_row = wr * 64 + lr + (q & 1) * 8;
    const int a_koff = (q >> 1) * 8;
    const int b_row = wc * 64 + lr + (q >> 1) * 8;
    const int b_koff = (q & 1) * 8;

    float acc[4][8][4];
#pragma unroll
    for (int mi = 0; mi < 4; ++mi)
#pragma unroll
        for (int ni = 0; ni < 8; ++ni)
#pragma unroll
            for (int e = 0; e < 4; ++e) acc[mi][ni][e] = 0.f;

    load_tile(smbase, rows0, n0, 0, t, 0);
    CP_COMMIT();

    for (int kt = 0; kt < NKT; ++kt) {
        const int p = kt & 1;
        if (kt + 1 < NKT) {
            load_tile(smbase, rows0, n0, kt + 1, t, p ^ 1);
            CP_COMMIT();
            CP_WAIT(1);
        } else {
            CP_WAIT(0);
        }
        __syncthreads();

        const uint32_t sa = smbase + p * BUFOFF;
        const uint32_t sb = sa + ABYTES;
#pragma unroll
        for (int ks = 0; ks < 4; ++ks) {
            const int k0 = ks * 16;
            uint32_t af[4][4], bf[8][2];
#pragma unroll
            for (int mi = 0; mi < 4; ++mi)
                ldsm_x4(af[mi][0], af[mi][1], af[mi][2], af[mi][3],
                        sa + (a_row + mi * 16) * ROWB + (k0 + a_koff) * 2);
#pragma unroll
            for (int np = 0; np < 4; ++np)
                ldsm_x4(bf[2 * np][0], bf[2 * np][1], bf[2 * np + 1][0], bf[2 * np + 1][1],
                        sb + (b_row + np * 16) * ROWB + (k0 + b_koff) * 2);
#pragma unroll
            for (int mi = 0; mi < 4; ++mi)
#pragma unroll
                for (int ni = 0; ni < 8; ++ni)
                    mma16816(acc[mi][ni], af[mi], bf[ni]);
        }
        __syncthreads();
    }

    // epilogue: s = C - 2M (fp16), stage in smem, coalesced write
    __half* ds = reinterpret_cast<__half*>(smraw);    // [128][136]
    const int g = lane >> 2, c = (lane & 3) * 2;
#pragma unroll
    for (int mi = 0; mi < 4; ++mi) {
        const int r0 = wr * 64 + mi * 16 + g;
#pragma unroll
        for (int ni = 0; ni < 8; ++ni) {
            const int col = wc * 64 + ni * 8 + c;
            const float cn0 = g_codenorm[n0 + col];
            const float cn1 = g_codenorm[n0 + col + 1];
            __half2 v0, v1;
            v0.x = __float2half_rn(fmaf(-2.f, acc[mi][ni][0], cn0));
            v0.y = __float2half_rn(fmaf(-2.f, acc[mi][ni][1], cn1));
            v1.x = __float2half_rn(fmaf(-2.f, acc[mi][ni][2], cn0));
            v1.y = __float2half_rn(fmaf(-2.f, acc[mi][ni][3], cn1));
            *reinterpret_cast<__half2*>(ds + r0 * 136 + col)       = v0;
            *reinterpret_cast<__half2*>(ds + (r0 + 8) * 136 + col) = v1;
        }
    }
    __syncthreads();
#pragma unroll
    for (int it = 0; it < 16; ++it) {
        const int row = wid * 32 + it * 2 + (lane >> 4);
        const int ch  = lane & 15;                       // 16B chunk within row
        uint4 v = *reinterpret_cast<const uint4*>(ds + row * 136 + ch * 8);
        *reinterpret_cast<uint4*>(g_score + (size_t)(rows0 + row) * 1024 + n0 + ch * 8) = v;
    }
}

// ---------------------------------------------------------------------------
// Select + exact rescore. One warp per row, fp16 scores.
// Unique candidate within margin => provably the exact argmin.
// Ambiguous => rescore candidates with the reference-exact chain.
// ---------------------------------------------------------------------------
__global__ void __launch_bounds__(256) select_kernel(const float* __restrict__ z,
                                                     const float* __restrict__ cb)
{
    __shared__ int s_list[8][64];
    __shared__ int s_cnt[8];
    const int warp = threadIdx.x >> 5, lane = threadIdx.x & 31;
    const int row = blockIdx.x * 8 + warp;
    const __half* sr = g_score + (size_t)row * 1024;
    if (lane == 0) s_cnt[warp] = 0;
    __syncwarp();

    float dv[32];
    unsigned long long key = ~0ull;
#pragma unroll
    for (int it = 0; it < 4; ++it) {
        uint4 raw = __ldg((const uint4*)sr + it * 32 + lane);
        const int i0 = (it * 32 + lane) * 8;
        const uint32_t w[4] = { raw.x, raw.y, raw.z, raw.w };
#pragma unroll
        for (int h = 0; h < 4; ++h) {
            float2 f = __half22float2(*reinterpret_cast<const __half2*>(&w[h]));
            dv[it * 8 + 2 * h]     = f.x;
            dv[it * 8 + 2 * h + 1] = f.y;
            unsigned long long k;
            k = ((unsigned long long)__float_as_uint(f.x + 1.0f) << 32) | (unsigned)(i0 + 2 * h);
            if (k < key) key = k;
            k = ((unsigned long long)__float_as_uint(f.y + 1.0f) << 32) | (unsigned)(i0 + 2 * h + 1);
            if (k < key) key = k;
        }
    }
#pragma unroll
    for (int o = 16; o > 0; o >>= 1) {
        unsigned long long other = __shfl_xor_sync(0xffffffffu, key, o);
        if (other < key) key = other;
    }
    // s in [-0.07, 0.07]; key uses s+1 > 0 so float bits are order-preserving.
    const float thr = (__uint_as_float((uint32_t)(key >> 32)) - 1.0f) + MARGIN;
#pragma unroll
    for (int it = 0; it < 4; ++it)
#pragma unroll
        for (int e = 0; e < 8; ++e)
            if (dv[it * 8 + e] <= thr) {
                int pos = atomicAdd(&s_cnt[warp], 1);
                if (pos < 64) s_list[warp][pos] = (it * 32 + lane) * 8 + e;
            }
    __syncwarp();
    const int cnt = s_cnt[warp];

    int winner;
    if (cnt <= 1) {
        winner = (int)(key & 0xFFFFFFFFull);    // unique candidate == exact argmin
    } else {
        const int b = row >> 10, hw = row & 1023;
        const float* zr = z + (size_t)b * DIM * HW + hw;
        const float Ar = g_rownorm[row];
        const bool full = (cnt > 64);           // safety fallback
        const int total = full ? 1024 : cnt;
        unsigned long long bk = ~0ull;
        for (int base = 0; base < total; base += 32) {
            const int ci = base + lane;
            unsigned long long k2 = ~0ull;
            if (ci < total) {
                const int cand = full ? ci : s_list[warp][ci];
                const float* wr = cb + (size_t)cand * DIM;
                float acc = 0.f;                 // reference-exact chain
#pragma unroll 8
                for (int c = 0; c < DIM; ++c)
                    acc = __fmaf_rn(zr[(size_t)c * HW], wr[c], acc);
                float d = __fadd_rn(__fadd_rn(Ar, __fmul_rn(-2.f, acc)),
                                    g_codenorm[cand]);
                k2 = ((unsigned long long)__float_as_uint(d) << 32) | (unsigned)cand;
            }
            if (k2 < bk) bk = k2;
        }
#pragma unroll
        for (int o = 16; o > 0; o >>= 1) {
            unsigned long long other = __shfl_xor_sync(0xffffffffu, bk, o);
            if (other < bk) bk = other;
        }
        winner = (int)(bk & 0xFFFFFFFFull);
    }
    if (lane == 0) g_index[row] = winner;
}

// ---------------------------------------------------------------------------
// Gather: quantized = codebook[idx]; also writes indices output.
// ---------------------------------------------------------------------------
__global__ void gather_kernel(const float* __restrict__ cb, float* __restrict__ out) {
    int i  = blockIdx.x * blockDim.x + threadIdx.x;
    int n  = i >> 7;
    int dd = i & 127;
    int idx = g_index[n];
    float4 v = __ldg(reinterpret_cast<const float4*>(cb) + (size_t)idx * 128 + dd);
    reinterpret_cast<float4*>(out)[i] = v;
    if (dd == 0) out[QUANT_ELEMS + n] = (float)idx;
}

// ---------------------------------------------------------------------------
extern "C" void kernel_launch(void* const* d_in, const int* in_sizes, int n_in,
                              void* d_out, int out_size) {
    const float* z  = (const float*)d_in[0];
    const float* cb = (const float*)d_in[1];
    float* out = (float*)d_out;

    cudaFuncSetAttribute(pass1_kernel,
                         cudaFuncAttributeMaxDynamicSharedMemorySize, P1_SMEM);

    prep_kernel<<<1024 + K_CODES / 32, 128>>>(z, cb);
    convert_z_kernel<<<(N_ROWS / 64) * 8, 256>>>(z);
    convert_w_kernel<<<K_CODES, 128>>>(cb);
    pass1_kernel<<<(N_ROWS / PM) * (K_CODES / PN), 128, P1_SMEM>>>();
    select_kernel<<<N_ROWS / 8, 256>>>(z, cb);
    gather_kernel<<<QUANT_ELEMS / 4 / 256, 256>>>(cb, out);
}